// round 10
// baseline (speedup 1.0000x reference)
#include <cuda_runtime.h>
#include <cuda_fp16.h>
#include <cuda_bf16.h>

#define NN 50000
#define EE 1600000
#define IN_F 128
#define HID_F 64
#define OUT_F 16

#define SCAN_B 1024
#define NBLK_SCAN ((NN + SCAN_B - 1) / SCAN_B)   // 49

typedef unsigned long long ull;

// ---------------- packed f32x2 helpers (sm_100+) ------------------------------
__device__ __forceinline__ ull pack2(float a, float b) {
    ull r; asm("mov.b64 %0, {%1, %2};" : "=l"(r) : "f"(a), "f"(b)); return r;
}
__device__ __forceinline__ void unpack2(ull v, float& a, float& b) {
    asm("mov.b64 {%0, %1}, %2;" : "=f"(a), "=f"(b) : "l"(v));
}
__device__ __forceinline__ void fma2(ull& acc, ull a, ull b) {
    asm("fma.rn.f32x2 %0, %1, %2, %3;" : "=l"(acc) : "l"(a), "l"(b), "l"(acc));
}

// ---------------- scratch (device globals; no allocation allowed) -------------
__device__ __half2 g_hh[NN * 32];      // layer-1 projected features (fp16, 64 cols)
__device__ float   g_h1[NN * HID_F];   // layer-1 output (post relu, fp32)
__device__ __half2 g_h2h[NN * 8];      // layer-2 projected features (fp16, 16 cols)
__device__ int   g_deg_in[NN];
__device__ int   g_deg_out[NN];
__device__ int   g_cursor[NN];
__device__ int   g_rowstart[NN];
__device__ int   g_csr[EE];            // src ids grouped by dst
__device__ int   g_blockSums[64];
__device__ int   g_blockOffsets[64];

// ---------------- K0: zero counters ------------------------------------------
__global__ void k_zero() {
    int i = blockIdx.x * blockDim.x + threadIdx.x;
    if (i < NN) { g_deg_in[i] = 0; g_deg_out[i] = 0; }
}

// ---------------- K1: degree histogram ----------------------------------------
__global__ void k_deg(const int* __restrict__ src, const int* __restrict__ dst) {
    int e = blockIdx.x * blockDim.x + threadIdx.x;
    if (e >= EE) return;
    atomicAdd(&g_deg_out[src[e]], 1);
    atomicAdd(&g_deg_in[dst[e]], 1);
}

// ---------------- K2a: per-chunk reduce ---------------------------------------
__global__ void k_scan_reduce() {
    __shared__ int warpsums[32];
    int i = blockIdx.x * SCAN_B + threadIdx.x;
    int v = (i < NN) ? g_deg_in[i] : 0;
    #pragma unroll
    for (int d = 16; d > 0; d >>= 1) v += __shfl_down_sync(0xffffffffu, v, d);
    if ((threadIdx.x & 31) == 0) warpsums[threadIdx.x >> 5] = v;
    __syncthreads();
    if (threadIdx.x < 32) {
        int w = warpsums[threadIdx.x];
        #pragma unroll
        for (int d = 16; d > 0; d >>= 1) w += __shfl_down_sync(0xffffffffu, w, d);
        if (threadIdx.x == 0) g_blockSums[blockIdx.x] = w;
    }
}

// ---------------- K2b: warp-parallel exclusive scan of 49 block sums ----------
__global__ void k_scan_blocks() {
    int l = threadIdx.x;               // 32 threads
    int i0 = 2 * l, i1 = 2 * l + 1;
    int v0 = (i0 < NBLK_SCAN) ? g_blockSums[i0] : 0;
    int v1 = (i1 < NBLK_SCAN) ? g_blockSums[i1] : 0;
    int s = v0 + v1;
    int inc = s;
    #pragma unroll
    for (int d = 1; d < 32; d <<= 1) {
        int t = __shfl_up_sync(0xffffffffu, inc, d);
        if (l >= d) inc += t;
    }
    int excl = inc - s;
    if (i0 < NBLK_SCAN) g_blockOffsets[i0] = excl;
    if (i1 < NBLK_SCAN) g_blockOffsets[i1] = excl + v0;
}

// ---------------- K2c: per-chunk exclusive scan -> rowstart + cursor ----------
__global__ void k_scan_chunks() {
    __shared__ int warpsums[32];
    int b = blockIdx.x;
    int i = b * SCAN_B + threadIdx.x;
    int lane = threadIdx.x & 31;
    int wid = threadIdx.x >> 5;
    int orig = (i < NN) ? g_deg_in[i] : 0;
    int v = orig;
    #pragma unroll
    for (int d = 1; d < 32; d <<= 1) {
        int t = __shfl_up_sync(0xffffffffu, v, d);
        if (lane >= d) v += t;
    }
    if (lane == 31) warpsums[wid] = v;
    __syncthreads();
    if (threadIdx.x < 32) {
        int w = warpsums[threadIdx.x];
        #pragma unroll
        for (int d = 1; d < 32; d <<= 1) {
            int t = __shfl_up_sync(0xffffffffu, w, d);
            if (threadIdx.x >= d) w += t;
        }
        warpsums[threadIdx.x] = w;
    }
    __syncthreads();
    int warpoff = (wid > 0) ? warpsums[wid - 1] : 0;
    int excl = (v - orig) + warpoff + g_blockOffsets[b];
    if (i < NN) { g_rowstart[i] = excl; g_cursor[i] = excl; }
}

// ---------------- K3: scatter edges into CSR (cursor pre-offset) --------------
__global__ void k_scatter(const int* __restrict__ src, const int* __restrict__ dst) {
    int e = blockIdx.x * blockDim.x + threadIdx.x;
    if (e >= EE) return;
    int p = atomicAdd(&g_cursor[dst[e]], 1);
    g_csr[p] = src[e];
}

// ---------------- K4: proj1  h = (x * norm_s) @ W1  (FFMA2, fp16 out) ---------
#define NT1 ((NN + 15) / 16)
__global__ void k_proj1(const float* __restrict__ feat, const float* __restrict__ W1) {
    __shared__ float sW[IN_F * HID_F];       // 32 KB
    __shared__ float sX[16][IN_F + 4];
    __shared__ float sNs[16];
    int tid = threadIdx.x;
    for (int idx = tid; idx < IN_F * HID_F; idx += 256) sW[idx] = W1[idx];

    for (int tile = blockIdx.x; tile < NT1; tile += gridDim.x) {
        __syncthreads();
        if (tid < 16) {
            int gn = tile * 16 + tid;
            float d = (gn < NN) ? (float)g_deg_out[gn] : 1.f;
            sNs[tid] = rsqrtf(fmaxf(d, 1.f));
        }
        __syncthreads();
        for (int idx = tid; idx < 16 * IN_F; idx += 256) {
            int nd = idx >> 7, k = idx & (IN_F - 1);
            int gn = tile * 16 + nd;
            sX[nd][k] = (gn < NN) ? feat[gn * IN_F + k] * sNs[nd] : 0.f;
        }
        __syncthreads();
        int cg = tid & 15, nd = tid >> 4;
        ull a0 = 0ull, a1 = 0ull;   // bit pattern of (0.f, 0.f)
        #pragma unroll 8
        for (int k = 0; k < IN_F; k++) {
            ulonglong2 w = *(const ulonglong2*)&sW[k * HID_F + cg * 4];
            float xv = sX[nd][k];
            ull xx = pack2(xv, xv);
            fma2(a0, w.x, xx);
            fma2(a1, w.y, xx);
        }
        int gn = tile * 16 + nd;
        if (gn < NN) {
            float f0, f1, f2, f3;
            unpack2(a0, f0, f1); unpack2(a1, f2, f3);
            __half2 hp[2] = { __floats2half2_rn(f0, f1), __floats2half2_rn(f2, f3) };
            *(uint2*)&g_hh[gn * 32 + cg * 2] = *(uint2*)hp;
        }
    }
}

// ---------------- K5: agg1  h1 = relu(segsum(h[src]) * norm_d + b1) -----------
// warp per node, lane holds col-pair (2l, 2l+1); fp16 gather rows (128B/row)
__global__ void k_agg1(const float* __restrict__ b1) {
    int gw = (blockIdx.x * blockDim.x + threadIdx.x) >> 5;
    int lane = threadIdx.x & 31;
    if (gw >= NN) return;
    int row = g_rowstart[gw];
    int deg = g_deg_in[gw];
    float2 acc = make_float2(0.f, 0.f);
    for (int i = 0; i < deg; i += 32) {
        int sidx = (i + lane < deg) ? g_csr[row + i + lane] : 0;
        int m = min(32, deg - i);
        int j = 0;
        for (; j + 4 <= m; j += 4) {
            int s0 = __shfl_sync(0xffffffffu, sidx, j);
            int s1 = __shfl_sync(0xffffffffu, sidx, j + 1);
            int s2 = __shfl_sync(0xffffffffu, sidx, j + 2);
            int s3 = __shfl_sync(0xffffffffu, sidx, j + 3);
            float2 v0 = __half22float2(g_hh[s0 * 32 + lane]);
            float2 v1 = __half22float2(g_hh[s1 * 32 + lane]);
            float2 v2 = __half22float2(g_hh[s2 * 32 + lane]);
            float2 v3 = __half22float2(g_hh[s3 * 32 + lane]);
            acc.x += (v0.x + v1.x) + (v2.x + v3.x);
            acc.y += (v0.y + v1.y) + (v2.y + v3.y);
        }
        for (; j < m; ++j) {
            int s = __shfl_sync(0xffffffffu, sidx, j);
            float2 v = __half22float2(g_hh[s * 32 + lane]);
            acc.x += v.x; acc.y += v.y;
        }
    }
    float nd = rsqrtf(fmaxf((float)deg, 1.f));
    float2 bb = ((const float2*)b1)[lane];
    float2 o;
    o.x = fmaxf(acc.x * nd + bb.x, 0.f);
    o.y = fmaxf(acc.y * nd + bb.y, 0.f);
    ((float2*)g_h1)[gw * 32 + lane] = o;
}

// ---------------- K6: proj2  h2 = (h1 * norm_s) @ W2  (FFMA2, fp16 out) -------
#define NT2 ((NN + 63) / 64)
__global__ void k_proj2(const float* __restrict__ W2) {
    __shared__ float sW[HID_F * OUT_F];     // 4 KB
    __shared__ float sX[64][HID_F + 4];
    __shared__ float sNs[64];
    int tid = threadIdx.x;
    int tile = blockIdx.x;
    for (int idx = tid; idx < HID_F * OUT_F; idx += 256) sW[idx] = W2[idx];
    if (tid < 64) {
        int gn = tile * 64 + tid;
        float d = (gn < NN) ? (float)g_deg_out[gn] : 1.f;
        sNs[tid] = rsqrtf(fmaxf(d, 1.f));
    }
    __syncthreads();
    for (int idx = tid; idx < 64 * HID_F; idx += 256) {
        int nd = idx >> 6, k = idx & (HID_F - 1);
        int gn = tile * 64 + nd;
        sX[nd][k] = (gn < NN) ? g_h1[gn * HID_F + k] * sNs[nd] : 0.f;
    }
    __syncthreads();
    int cg = tid & 3, nd = tid >> 2;
    ull a0 = 0ull, a1 = 0ull;
    #pragma unroll
    for (int k = 0; k < HID_F; k++) {
        ulonglong2 w = *(const ulonglong2*)&sW[k * OUT_F + cg * 4];
        float xv = sX[nd][k];
        ull xx = pack2(xv, xv);
        fma2(a0, w.x, xx);
        fma2(a1, w.y, xx);
    }
    int gn = tile * 64 + nd;
    if (gn < NN) {
        float f0, f1, f2, f3;
        unpack2(a0, f0, f1); unpack2(a1, f2, f3);
        __half2 hp[2] = { __floats2half2_rn(f0, f1), __floats2half2_rn(f2, f3) };
        *(uint2*)&g_h2h[gn * 8 + cg * 2] = *(uint2*)hp;
    }
}

// ---------------- K7: agg2  out = segsum(h2[src]) * norm_d + b2 ---------------
// warp per node, 4 edges in flight: 8 lanes per edge (fp16 row = 32B = 8x half2)
__global__ void k_agg2(const float* __restrict__ b2, float* __restrict__ out) {
    int gw = (blockIdx.x * blockDim.x + threadIdx.x) >> 5;
    int lane = threadIdx.x & 31;
    if (gw >= NN) return;
    int row = g_rowstart[gw];
    int deg = g_deg_in[gw];
    int sub = lane >> 3;    // edge subgroup 0..3
    int cp  = lane & 7;     // column pair 0..7
    float2 acc = make_float2(0.f, 0.f);
    for (int i = 0; i < deg; i += 32) {
        int sidx = (i + lane < deg) ? g_csr[row + i + lane] : 0;
        int m = min(32, deg - i);
        for (int j = 0; j < m; j += 4) {
            int e = j + sub;
            int s = __shfl_sync(0xffffffffu, sidx, e);
            if (e < m) {
                float2 v = __half22float2(g_h2h[s * 8 + cp]);
                acc.x += v.x; acc.y += v.y;
            }
        }
    }
    acc.x += __shfl_down_sync(0xffffffffu, acc.x, 16);
    acc.y += __shfl_down_sync(0xffffffffu, acc.y, 16);
    acc.x += __shfl_down_sync(0xffffffffu, acc.x, 8);
    acc.y += __shfl_down_sync(0xffffffffu, acc.y, 8);
    if (lane < 8) {
        float nd = rsqrtf(fmaxf((float)deg, 1.f));
        float2 bb = ((const float2*)b2)[lane];
        float2 o;
        o.x = acc.x * nd + bb.x;
        o.y = acc.y * nd + bb.y;
        ((float2*)out)[gw * 8 + lane] = o;
    }
}

// ---------------- launch ------------------------------------------------------
extern "C" void kernel_launch(void* const* d_in, const int* in_sizes, int n_in,
                              void* d_out, int out_size) {
    const float* feat = (const float*)d_in[0];
    const float* W1   = (const float*)d_in[1];
    const float* b1   = (const float*)d_in[2];
    const float* W2   = (const float*)d_in[3];
    const float* b2   = (const float*)d_in[4];
    const int*   src  = (const int*)d_in[5];
    const int*   dst  = (const int*)d_in[6];
    float*       out  = (float*)d_out;

    const int EB  = (EE + 255) / 256;
    const int AGB = (NN + 7) / 8;

    k_zero<<<(NN + 255) / 256, 256>>>();
    k_deg<<<EB, 256>>>(src, dst);
    k_scan_reduce<<<NBLK_SCAN, SCAN_B>>>();
    k_scan_blocks<<<1, 32>>>();
    k_scan_chunks<<<NBLK_SCAN, SCAN_B>>>();
    k_scatter<<<EB, 256>>>(src, dst);
    k_proj1<<<592, 256>>>(feat, W1);
    k_agg1<<<AGB, 256>>>(b1);
    k_proj2<<<NT2, 256>>>(W2);
    k_agg2<<<AGB, 256>>>(b2, out);
}

// round 11
// speedup vs baseline: 1.0006x; 1.0006x over previous
#include <cuda_runtime.h>
#include <cuda_fp16.h>
#include <cuda_bf16.h>

#define NN 50000
#define EE 1600000
#define IN_F 128
#define HID_F 64
#define OUT_F 16

#define SCAN_B 1024
#define NBLK_SCAN ((NN + SCAN_B - 1) / SCAN_B)   // 49

typedef unsigned long long ull;

// ---------------- packed f32x2 helpers (sm_100+) ------------------------------
__device__ __forceinline__ ull pack2(float a, float b) {
    ull r; asm("mov.b64 %0, {%1, %2};" : "=l"(r) : "f"(a), "f"(b)); return r;
}
__device__ __forceinline__ void unpack2(ull v, float& a, float& b) {
    asm("mov.b64 {%0, %1}, %2;" : "=f"(a), "=f"(b) : "l"(v));
}
__device__ __forceinline__ void fma2(ull& acc, ull a, ull b) {
    asm("fma.rn.f32x2 %0, %1, %2, %3;" : "=l"(acc) : "l"(a), "l"(b), "l"(acc));
}

// ---------------- scratch (device globals; no allocation allowed) -------------
__device__ __half2 g_hh[NN * 32];      // layer-1 projected features (fp16, 64 cols)
__device__ float   g_h1[NN * HID_F];   // layer-1 output (post relu, fp32)
__device__ __half2 g_h2h[NN * 8];      // layer-2 projected features (fp16, 16 cols)
__device__ int   g_deg_in[NN];
__device__ int   g_deg_out[NN];
__device__ int   g_cursor[NN];
__device__ int   g_rowstart[NN];
__device__ int   g_csr[EE];            // src ids grouped by dst
__device__ int   g_blockSums[64];
__device__ int   g_blockOffsets[64];

// ---------------- K0: zero counters ------------------------------------------
__global__ void k_zero() {
    int i = blockIdx.x * blockDim.x + threadIdx.x;
    if (i < NN) { g_deg_in[i] = 0; g_deg_out[i] = 0; }
}

// ---------------- K1: degree histogram ----------------------------------------
__global__ void k_deg(const int* __restrict__ src, const int* __restrict__ dst) {
    int e = blockIdx.x * blockDim.x + threadIdx.x;
    if (e >= EE) return;
    atomicAdd(&g_deg_out[src[e]], 1);
    atomicAdd(&g_deg_in[dst[e]], 1);
}

// ---------------- K2a: per-chunk reduce ---------------------------------------
__global__ void k_scan_reduce() {
    __shared__ int warpsums[32];
    int i = blockIdx.x * SCAN_B + threadIdx.x;
    int v = (i < NN) ? g_deg_in[i] : 0;
    #pragma unroll
    for (int d = 16; d > 0; d >>= 1) v += __shfl_down_sync(0xffffffffu, v, d);
    if ((threadIdx.x & 31) == 0) warpsums[threadIdx.x >> 5] = v;
    __syncthreads();
    if (threadIdx.x < 32) {
        int w = warpsums[threadIdx.x];
        #pragma unroll
        for (int d = 16; d > 0; d >>= 1) w += __shfl_down_sync(0xffffffffu, w, d);
        if (threadIdx.x == 0) g_blockSums[blockIdx.x] = w;
    }
}

// ---------------- K2b: warp-parallel exclusive scan of 49 block sums ----------
__global__ void k_scan_blocks() {
    int l = threadIdx.x;               // 32 threads
    int i0 = 2 * l, i1 = 2 * l + 1;
    int v0 = (i0 < NBLK_SCAN) ? g_blockSums[i0] : 0;
    int v1 = (i1 < NBLK_SCAN) ? g_blockSums[i1] : 0;
    int s = v0 + v1;
    int inc = s;
    #pragma unroll
    for (int d = 1; d < 32; d <<= 1) {
        int t = __shfl_up_sync(0xffffffffu, inc, d);
        if (l >= d) inc += t;
    }
    int excl = inc - s;
    if (i0 < NBLK_SCAN) g_blockOffsets[i0] = excl;
    if (i1 < NBLK_SCAN) g_blockOffsets[i1] = excl + v0;
}

// ---------------- K2c: per-chunk exclusive scan -> rowstart + cursor ----------
__global__ void k_scan_chunks() {
    __shared__ int warpsums[32];
    int b = blockIdx.x;
    int i = b * SCAN_B + threadIdx.x;
    int lane = threadIdx.x & 31;
    int wid = threadIdx.x >> 5;
    int orig = (i < NN) ? g_deg_in[i] : 0;
    int v = orig;
    #pragma unroll
    for (int d = 1; d < 32; d <<= 1) {
        int t = __shfl_up_sync(0xffffffffu, v, d);
        if (lane >= d) v += t;
    }
    if (lane == 31) warpsums[wid] = v;
    __syncthreads();
    if (threadIdx.x < 32) {
        int w = warpsums[threadIdx.x];
        #pragma unroll
        for (int d = 1; d < 32; d <<= 1) {
            int t = __shfl_up_sync(0xffffffffu, w, d);
            if (threadIdx.x >= d) w += t;
        }
        warpsums[threadIdx.x] = w;
    }
    __syncthreads();
    int warpoff = (wid > 0) ? warpsums[wid - 1] : 0;
    int excl = (v - orig) + warpoff + g_blockOffsets[b];
    if (i < NN) { g_rowstart[i] = excl; g_cursor[i] = excl; }
}

// ---------------- K3: scatter edges into CSR (cursor pre-offset) --------------
__global__ void k_scatter(const int* __restrict__ src, const int* __restrict__ dst) {
    int e = blockIdx.x * blockDim.x + threadIdx.x;
    if (e >= EE) return;
    int p = atomicAdd(&g_cursor[dst[e]], 1);
    g_csr[p] = src[e];
}

// ---------------- K4: proj1  h = (x * norm_s) @ W1  (FFMA2, fp16 out) ---------
#define NT1 ((NN + 15) / 16)
__global__ void k_proj1(const float* __restrict__ feat, const float* __restrict__ W1) {
    __shared__ float sW[IN_F * HID_F];       // 32 KB
    __shared__ float sX[16][IN_F + 4];
    __shared__ float sNs[16];
    int tid = threadIdx.x;
    for (int idx = tid; idx < IN_F * HID_F; idx += 256) sW[idx] = W1[idx];

    for (int tile = blockIdx.x; tile < NT1; tile += gridDim.x) {
        __syncthreads();
        if (tid < 16) {
            int gn = tile * 16 + tid;
            float d = (gn < NN) ? (float)g_deg_out[gn] : 1.f;
            sNs[tid] = rsqrtf(fmaxf(d, 1.f));
        }
        __syncthreads();
        for (int idx = tid; idx < 16 * IN_F; idx += 256) {
            int nd = idx >> 7, k = idx & (IN_F - 1);
            int gn = tile * 16 + nd;
            sX[nd][k] = (gn < NN) ? feat[gn * IN_F + k] * sNs[nd] : 0.f;
        }
        __syncthreads();
        int cg = tid & 15, nd = tid >> 4;
        ull a0 = 0ull, a1 = 0ull;   // bit pattern of (0.f, 0.f)
        #pragma unroll 8
        for (int k = 0; k < IN_F; k++) {
            ulonglong2 w = *(const ulonglong2*)&sW[k * HID_F + cg * 4];
            float xv = sX[nd][k];
            ull xx = pack2(xv, xv);
            fma2(a0, w.x, xx);
            fma2(a1, w.y, xx);
        }
        int gn = tile * 16 + nd;
        if (gn < NN) {
            float f0, f1, f2, f3;
            unpack2(a0, f0, f1); unpack2(a1, f2, f3);
            __half2 hp[2] = { __floats2half2_rn(f0, f1), __floats2half2_rn(f2, f3) };
            *(uint2*)&g_hh[gn * 32 + cg * 2] = *(uint2*)hp;
        }
    }
}

// ---------------- K5: agg1  h1 = relu(segsum(h[src]) * norm_d + b1) -----------
// warp per node, lane holds col-pair (2l, 2l+1); fp16 gather rows (128B/row)
__global__ void k_agg1(const float* __restrict__ b1) {
    int gw = (blockIdx.x * blockDim.x + threadIdx.x) >> 5;
    int lane = threadIdx.x & 31;
    if (gw >= NN) return;
    int row = g_rowstart[gw];
    int deg = g_deg_in[gw];
    float2 acc = make_float2(0.f, 0.f);
    for (int i = 0; i < deg; i += 32) {
        int sidx = (i + lane < deg) ? g_csr[row + i + lane] : 0;
        int m = min(32, deg - i);
        int j = 0;
        for (; j + 4 <= m; j += 4) {
            int s0 = __shfl_sync(0xffffffffu, sidx, j);
            int s1 = __shfl_sync(0xffffffffu, sidx, j + 1);
            int s2 = __shfl_sync(0xffffffffu, sidx, j + 2);
            int s3 = __shfl_sync(0xffffffffu, sidx, j + 3);
            float2 v0 = __half22float2(g_hh[s0 * 32 + lane]);
            float2 v1 = __half22float2(g_hh[s1 * 32 + lane]);
            float2 v2 = __half22float2(g_hh[s2 * 32 + lane]);
            float2 v3 = __half22float2(g_hh[s3 * 32 + lane]);
            acc.x += (v0.x + v1.x) + (v2.x + v3.x);
            acc.y += (v0.y + v1.y) + (v2.y + v3.y);
        }
        for (; j < m; ++j) {
            int s = __shfl_sync(0xffffffffu, sidx, j);
            float2 v = __half22float2(g_hh[s * 32 + lane]);
            acc.x += v.x; acc.y += v.y;
        }
    }
    float nd = rsqrtf(fmaxf((float)deg, 1.f));
    float2 bb = ((const float2*)b1)[lane];
    float2 o;
    o.x = fmaxf(acc.x * nd + bb.x, 0.f);
    o.y = fmaxf(acc.y * nd + bb.y, 0.f);
    ((float2*)g_h1)[gw * 32 + lane] = o;
}

// ---------------- K6: proj2  h2 = (h1 * norm_s) @ W2  (FFMA2, fp16 out) -------
#define NT2 ((NN + 63) / 64)
__global__ void k_proj2(const float* __restrict__ W2) {
    __shared__ float sW[HID_F * OUT_F];     // 4 KB
    __shared__ float sX[64][HID_F + 4];
    __shared__ float sNs[64];
    int tid = threadIdx.x;
    int tile = blockIdx.x;
    for (int idx = tid; idx < HID_F * OUT_F; idx += 256) sW[idx] = W2[idx];
    if (tid < 64) {
        int gn = tile * 64 + tid;
        float d = (gn < NN) ? (float)g_deg_out[gn] : 1.f;
        sNs[tid] = rsqrtf(fmaxf(d, 1.f));
    }
    __syncthreads();
    for (int idx = tid; idx < 64 * HID_F; idx += 256) {
        int nd = idx >> 6, k = idx & (HID_F - 1);
        int gn = tile * 64 + nd;
        sX[nd][k] = (gn < NN) ? g_h1[gn * HID_F + k] * sNs[nd] : 0.f;
    }
    __syncthreads();
    int cg = tid & 3, nd = tid >> 2;
    ull a0 = 0ull, a1 = 0ull;
    #pragma unroll
    for (int k = 0; k < HID_F; k++) {
        ulonglong2 w = *(const ulonglong2*)&sW[k * OUT_F + cg * 4];
        float xv = sX[nd][k];
        ull xx = pack2(xv, xv);
        fma2(a0, w.x, xx);
        fma2(a1, w.y, xx);
    }
    int gn = tile * 64 + nd;
    if (gn < NN) {
        float f0, f1, f2, f3;
        unpack2(a0, f0, f1); unpack2(a1, f2, f3);
        __half2 hp[2] = { __floats2half2_rn(f0, f1), __floats2half2_rn(f2, f3) };
        *(uint2*)&g_h2h[gn * 8 + cg * 2] = *(uint2*)hp;
    }
}

// ---------------- K7: agg2  out = segsum(h2[src]) * norm_d + b2 ---------------
// warp per node, 4 edges in flight: 8 lanes per edge (fp16 row = 32B = 8x half2)
__global__ void k_agg2(const float* __restrict__ b2, float* __restrict__ out) {
    int gw = (blockIdx.x * blockDim.x + threadIdx.x) >> 5;
    int lane = threadIdx.x & 31;
    if (gw >= NN) return;
    int row = g_rowstart[gw];
    int deg = g_deg_in[gw];
    int sub = lane >> 3;    // edge subgroup 0..3
    int cp  = lane & 7;     // column pair 0..7
    float2 acc = make_float2(0.f, 0.f);
    for (int i = 0; i < deg; i += 32) {
        int sidx = (i + lane < deg) ? g_csr[row + i + lane] : 0;
        int m = min(32, deg - i);
        for (int j = 0; j < m; j += 4) {
            int e = j + sub;
            int s = __shfl_sync(0xffffffffu, sidx, e);
            if (e < m) {
                float2 v = __half22float2(g_h2h[s * 8 + cp]);
                acc.x += v.x; acc.y += v.y;
            }
        }
    }
    acc.x += __shfl_down_sync(0xffffffffu, acc.x, 16);
    acc.y += __shfl_down_sync(0xffffffffu, acc.y, 16);
    acc.x += __shfl_down_sync(0xffffffffu, acc.x, 8);
    acc.y += __shfl_down_sync(0xffffffffu, acc.y, 8);
    if (lane < 8) {
        float nd = rsqrtf(fmaxf((float)deg, 1.f));
        float2 bb = ((const float2*)b2)[lane];
        float2 o;
        o.x = acc.x * nd + bb.x;
        o.y = acc.y * nd + bb.y;
        ((float2*)out)[gw * 8 + lane] = o;
    }
}

// ---------------- launch ------------------------------------------------------
extern "C" void kernel_launch(void* const* d_in, const int* in_sizes, int n_in,
                              void* d_out, int out_size) {
    const float* feat = (const float*)d_in[0];
    const float* W1   = (const float*)d_in[1];
    const float* b1   = (const float*)d_in[2];
    const float* W2   = (const float*)d_in[3];
    const float* b2   = (const float*)d_in[4];
    const int*   src  = (const int*)d_in[5];
    const int*   dst  = (const int*)d_in[6];
    float*       out  = (float*)d_out;

    const int EB  = (EE + 255) / 256;
    const int AGB = (NN + 7) / 8;

    k_zero<<<(NN + 255) / 256, 256>>>();
    k_deg<<<EB, 256>>>(src, dst);
    k_scan_reduce<<<NBLK_SCAN, SCAN_B>>>();
    k_scan_blocks<<<1, 32>>>();
    k_scan_chunks<<<NBLK_SCAN, SCAN_B>>>();
    k_scatter<<<EB, 256>>>(src, dst);
    k_proj1<<<592, 256>>>(feat, W1);
    k_agg1<<<AGB, 256>>>(b1);
    k_proj2<<<NT2, 256>>>(W2);
    k_agg2<<<AGB, 256>>>(b2, out);
}

// round 12
// speedup vs baseline: 1.0029x; 1.0023x over previous
#include <cuda_runtime.h>
#include <cuda_fp16.h>
#include <cuda_bf16.h>

#define NN 50000
#define EE 1600000
#define IN_F 128
#define HID_F 64
#define OUT_F 16

#define SCAN_B 1024
#define NBLK_SCAN ((NN + SCAN_B - 1) / SCAN_B)   // 49

typedef unsigned long long ull;

// ---------------- packed f32x2 helpers (sm_100+) ------------------------------
__device__ __forceinline__ ull pack2(float a, float b) {
    ull r; asm("mov.b64 %0, {%1, %2};" : "=l"(r) : "f"(a), "f"(b)); return r;
}
__device__ __forceinline__ void unpack2(ull v, float& a, float& b) {
    asm("mov.b64 {%0, %1}, %2;" : "=f"(a), "=f"(b) : "l"(v));
}
__device__ __forceinline__ void fma2(ull& acc, ull a, ull b) {
    asm("fma.rn.f32x2 %0, %1, %2, %3;" : "=l"(acc) : "l"(a), "l"(b), "l"(acc));
}

// ---------------- scratch (device globals; no allocation allowed) -------------
__device__ __half2 g_hh[NN * 32];      // layer-1 projected features (fp16, 64 cols)
__device__ float   g_h1[NN * HID_F];   // layer-1 output (post relu, fp32)
__device__ __half2 g_h2h[NN * 8];      // layer-2 projected features (fp16, 16 cols)
__device__ int   g_deg_in[NN];
__device__ int   g_deg_out[NN];
__device__ int   g_cursor[NN];
__device__ int   g_rowstart[NN];
__device__ int   g_csr[EE];            // src ids grouped by dst
__device__ int   g_blockSums[64];
__device__ int   g_blockOffsets[64];

// ---------------- K0: zero counters ------------------------------------------
__global__ void k_zero() {
    int i = blockIdx.x * blockDim.x + threadIdx.x;
    if (i < NN) { g_deg_in[i] = 0; g_deg_out[i] = 0; }
}

// ---------------- K1: degree histogram ----------------------------------------
__global__ void k_deg(const int* __restrict__ src, const int* __restrict__ dst) {
    int e = blockIdx.x * blockDim.x + threadIdx.x;
    if (e >= EE) return;
    atomicAdd(&g_deg_out[src[e]], 1);
    atomicAdd(&g_deg_in[dst[e]], 1);
}

// ---------------- K2a: per-chunk reduce ---------------------------------------
__global__ void k_scan_reduce() {
    __shared__ int warpsums[32];
    int i = blockIdx.x * SCAN_B + threadIdx.x;
    int v = (i < NN) ? g_deg_in[i] : 0;
    #pragma unroll
    for (int d = 16; d > 0; d >>= 1) v += __shfl_down_sync(0xffffffffu, v, d);
    if ((threadIdx.x & 31) == 0) warpsums[threadIdx.x >> 5] = v;
    __syncthreads();
    if (threadIdx.x < 32) {
        int w = warpsums[threadIdx.x];
        #pragma unroll
        for (int d = 16; d > 0; d >>= 1) w += __shfl_down_sync(0xffffffffu, w, d);
        if (threadIdx.x == 0) g_blockSums[blockIdx.x] = w;
    }
}

// ---------------- K2b: warp-parallel exclusive scan of 49 block sums ----------
__global__ void k_scan_blocks() {
    int l = threadIdx.x;               // 32 threads
    int i0 = 2 * l, i1 = 2 * l + 1;
    int v0 = (i0 < NBLK_SCAN) ? g_blockSums[i0] : 0;
    int v1 = (i1 < NBLK_SCAN) ? g_blockSums[i1] : 0;
    int s = v0 + v1;
    int inc = s;
    #pragma unroll
    for (int d = 1; d < 32; d <<= 1) {
        int t = __shfl_up_sync(0xffffffffu, inc, d);
        if (l >= d) inc += t;
    }
    int excl = inc - s;
    if (i0 < NBLK_SCAN) g_blockOffsets[i0] = excl;
    if (i1 < NBLK_SCAN) g_blockOffsets[i1] = excl + v0;
}

// ---------------- K2c: per-chunk exclusive scan -> rowstart + cursor ----------
__global__ void k_scan_chunks() {
    __shared__ int warpsums[32];
    int b = blockIdx.x;
    int i = b * SCAN_B + threadIdx.x;
    int lane = threadIdx.x & 31;
    int wid = threadIdx.x >> 5;
    int orig = (i < NN) ? g_deg_in[i] : 0;
    int v = orig;
    #pragma unroll
    for (int d = 1; d < 32; d <<= 1) {
        int t = __shfl_up_sync(0xffffffffu, v, d);
        if (lane >= d) v += t;
    }
    if (lane == 31) warpsums[wid] = v;
    __syncthreads();
    if (threadIdx.x < 32) {
        int w = warpsums[threadIdx.x];
        #pragma unroll
        for (int d = 1; d < 32; d <<= 1) {
            int t = __shfl_up_sync(0xffffffffu, w, d);
            if (threadIdx.x >= d) w += t;
        }
        warpsums[threadIdx.x] = w;
    }
    __syncthreads();
    int warpoff = (wid > 0) ? warpsums[wid - 1] : 0;
    int excl = (v - orig) + warpoff + g_blockOffsets[b];
    if (i < NN) { g_rowstart[i] = excl; g_cursor[i] = excl; }
}

// ---------------- K3: scatter edges into CSR (cursor pre-offset) --------------
__global__ void k_scatter(const int* __restrict__ src, const int* __restrict__ dst) {
    int e = blockIdx.x * blockDim.x + threadIdx.x;
    if (e >= EE) return;
    int p = atomicAdd(&g_cursor[dst[e]], 1);
    g_csr[p] = src[e];
}

// ---------------- K4: proj1  h = (x * norm_s) @ W1  (FFMA2, fp16 out) ---------
#define NT1 ((NN + 15) / 16)
__global__ void k_proj1(const float* __restrict__ feat, const float* __restrict__ W1) {
    __shared__ float sW[IN_F * HID_F];       // 32 KB
    __shared__ float sX[16][IN_F + 4];
    __shared__ float sNs[16];
    int tid = threadIdx.x;
    for (int idx = tid; idx < IN_F * HID_F; idx += 256) sW[idx] = W1[idx];

    for (int tile = blockIdx.x; tile < NT1; tile += gridDim.x) {
        __syncthreads();
        if (tid < 16) {
            int gn = tile * 16 + tid;
            float d = (gn < NN) ? (float)g_deg_out[gn] : 1.f;
            sNs[tid] = rsqrtf(fmaxf(d, 1.f));
        }
        __syncthreads();
        for (int idx = tid; idx < 16 * IN_F; idx += 256) {
            int nd = idx >> 7, k = idx & (IN_F - 1);
            int gn = tile * 16 + nd;
            sX[nd][k] = (gn < NN) ? feat[gn * IN_F + k] * sNs[nd] : 0.f;
        }
        __syncthreads();
        int cg = tid & 15, nd = tid >> 4;
        ull a0 = 0ull, a1 = 0ull;   // bit pattern of (0.f, 0.f)
        #pragma unroll 8
        for (int k = 0; k < IN_F; k++) {
            ulonglong2 w = *(const ulonglong2*)&sW[k * HID_F + cg * 4];
            float xv = sX[nd][k];
            ull xx = pack2(xv, xv);
            fma2(a0, w.x, xx);
            fma2(a1, w.y, xx);
        }
        int gn = tile * 16 + nd;
        if (gn < NN) {
            float f0, f1, f2, f3;
            unpack2(a0, f0, f1); unpack2(a1, f2, f3);
            __half2 hp[2] = { __floats2half2_rn(f0, f1), __floats2half2_rn(f2, f3) };
            *(uint2*)&g_hh[gn * 32 + cg * 2] = *(uint2*)hp;
        }
    }
}

// ---------------- K5: agg1  h1 = relu(segsum(h[src]) * norm_d + b1) -----------
// warp per node, lane holds col-pair (2l, 2l+1); fp16 gather rows (128B/row)
__global__ void k_agg1(const float* __restrict__ b1) {
    int gw = (blockIdx.x * blockDim.x + threadIdx.x) >> 5;
    int lane = threadIdx.x & 31;
    if (gw >= NN) return;
    int row = g_rowstart[gw];
    int deg = g_deg_in[gw];
    float2 acc = make_float2(0.f, 0.f);
    for (int i = 0; i < deg; i += 32) {
        int sidx = (i + lane < deg) ? g_csr[row + i + lane] : 0;
        int m = min(32, deg - i);
        int j = 0;
        for (; j + 4 <= m; j += 4) {
            int s0 = __shfl_sync(0xffffffffu, sidx, j);
            int s1 = __shfl_sync(0xffffffffu, sidx, j + 1);
            int s2 = __shfl_sync(0xffffffffu, sidx, j + 2);
            int s3 = __shfl_sync(0xffffffffu, sidx, j + 3);
            float2 v0 = __half22float2(g_hh[s0 * 32 + lane]);
            float2 v1 = __half22float2(g_hh[s1 * 32 + lane]);
            float2 v2 = __half22float2(g_hh[s2 * 32 + lane]);
            float2 v3 = __half22float2(g_hh[s3 * 32 + lane]);
            acc.x += (v0.x + v1.x) + (v2.x + v3.x);
            acc.y += (v0.y + v1.y) + (v2.y + v3.y);
        }
        for (; j < m; ++j) {
            int s = __shfl_sync(0xffffffffu, sidx, j);
            float2 v = __half22float2(g_hh[s * 32 + lane]);
            acc.x += v.x; acc.y += v.y;
        }
    }
    float nd = rsqrtf(fmaxf((float)deg, 1.f));
    float2 bb = ((const float2*)b1)[lane];
    float2 o;
    o.x = fmaxf(acc.x * nd + bb.x, 0.f);
    o.y = fmaxf(acc.y * nd + bb.y, 0.f);
    ((float2*)g_h1)[gw * 32 + lane] = o;
}

// ---------------- K6: proj2  h2 = (h1 * norm_s) @ W2  (FFMA2, fp16 out) -------
#define NT2 ((NN + 63) / 64)
__global__ void k_proj2(const float* __restrict__ W2) {
    __shared__ float sW[HID_F * OUT_F];     // 4 KB
    __shared__ float sX[64][HID_F + 4];
    __shared__ float sNs[64];
    int tid = threadIdx.x;
    int tile = blockIdx.x;
    for (int idx = tid; idx < HID_F * OUT_F; idx += 256) sW[idx] = W2[idx];
    if (tid < 64) {
        int gn = tile * 64 + tid;
        float d = (gn < NN) ? (float)g_deg_out[gn] : 1.f;
        sNs[tid] = rsqrtf(fmaxf(d, 1.f));
    }
    __syncthreads();
    for (int idx = tid; idx < 64 * HID_F; idx += 256) {
        int nd = idx >> 6, k = idx & (HID_F - 1);
        int gn = tile * 64 + nd;
        sX[nd][k] = (gn < NN) ? g_h1[gn * HID_F + k] * sNs[nd] : 0.f;
    }
    __syncthreads();
    int cg = tid & 3, nd = tid >> 2;
    ull a0 = 0ull, a1 = 0ull;
    #pragma unroll
    for (int k = 0; k < HID_F; k++) {
        ulonglong2 w = *(const ulonglong2*)&sW[k * OUT_F + cg * 4];
        float xv = sX[nd][k];
        ull xx = pack2(xv, xv);
        fma2(a0, w.x, xx);
        fma2(a1, w.y, xx);
    }
    int gn = tile * 64 + nd;
    if (gn < NN) {
        float f0, f1, f2, f3;
        unpack2(a0, f0, f1); unpack2(a1, f2, f3);
        __half2 hp[2] = { __floats2half2_rn(f0, f1), __floats2half2_rn(f2, f3) };
        *(uint2*)&g_h2h[gn * 8 + cg * 2] = *(uint2*)hp;
    }
}

// ---------------- K7: agg2  out = segsum(h2[src]) * norm_d + b2 ---------------
// warp per node, 4 edges in flight: 8 lanes per edge (fp16 row = 32B = 8x half2)
__global__ void k_agg2(const float* __restrict__ b2, float* __restrict__ out) {
    int gw = (blockIdx.x * blockDim.x + threadIdx.x) >> 5;
    int lane = threadIdx.x & 31;
    if (gw >= NN) return;
    int row = g_rowstart[gw];
    int deg = g_deg_in[gw];
    int sub = lane >> 3;    // edge subgroup 0..3
    int cp  = lane & 7;     // column pair 0..7
    float2 acc = make_float2(0.f, 0.f);
    for (int i = 0; i < deg; i += 32) {
        int sidx = (i + lane < deg) ? g_csr[row + i + lane] : 0;
        int m = min(32, deg - i);
        for (int j = 0; j < m; j += 4) {
            int e = j + sub;
            int s = __shfl_sync(0xffffffffu, sidx, e);
            if (e < m) {
                float2 v = __half22float2(g_h2h[s * 8 + cp]);
                acc.x += v.x; acc.y += v.y;
            }
        }
    }
    acc.x += __shfl_down_sync(0xffffffffu, acc.x, 16);
    acc.y += __shfl_down_sync(0xffffffffu, acc.y, 16);
    acc.x += __shfl_down_sync(0xffffffffu, acc.x, 8);
    acc.y += __shfl_down_sync(0xffffffffu, acc.y, 8);
    if (lane < 8) {
        float nd = rsqrtf(fmaxf((float)deg, 1.f));
        float2 bb = ((const float2*)b2)[lane];
        float2 o;
        o.x = acc.x * nd + bb.x;
        o.y = acc.y * nd + bb.y;
        ((float2*)out)[gw * 8 + lane] = o;
    }
}

// ---------------- launch ------------------------------------------------------
extern "C" void kernel_launch(void* const* d_in, const int* in_sizes, int n_in,
                              void* d_out, int out_size) {
    const float* feat = (const float*)d_in[0];
    const float* W1   = (const float*)d_in[1];
    const float* b1   = (const float*)d_in[2];
    const float* W2   = (const float*)d_in[3];
    const float* b2   = (const float*)d_in[4];
    const int*   src  = (const int*)d_in[5];
    const int*   dst  = (const int*)d_in[6];
    float*       out  = (float*)d_out;

    const int EB  = (EE + 255) / 256;
    const int AGB = (NN + 7) / 8;

    k_zero<<<(NN + 255) / 256, 256>>>();
    k_deg<<<EB, 256>>>(src, dst);
    k_scan_reduce<<<NBLK_SCAN, SCAN_B>>>();
    k_scan_blocks<<<1, 32>>>();
    k_scan_chunks<<<NBLK_SCAN, SCAN_B>>>();
    k_scatter<<<EB, 256>>>(src, dst);
    k_proj1<<<592, 256>>>(feat, W1);
    k_agg1<<<AGB, 256>>>(b1);
    k_proj2<<<NT2, 256>>>(W2);
    k_agg2<<<AGB, 256>>>(b2, out);
}